// round 12
// baseline (speedup 1.0000x reference)
#include <cuda_runtime.h>
#include <cuda_fp16.h>
#include <cstdint>

#define BDIM  16384
#define HID   4096
#define TS    4
#define CH    1024
#define LHH   256
#define G4    1024
#define TOT   2048
#define BT    65536

#if defined(__CUDA_ARCH__) && (defined(__CUDA_ARCH_FEAT_SM103_ALL) || defined(__CUDA_ARCH_FEAT_SM100_ALL))
#define TC_OK 1
#endif

// ---------------- scratch (device globals: allocation-free) ----------------
__device__ __align__(256) __half g_Xh[(size_t)BT * CH];
__device__ __align__(256) __half g_G[(size_t)BT * TOT];
__device__ __align__(256) __half g_Wc[TOT * CH];
__device__ __align__(256) __half g_Whh[2][G4 * LHH];
__device__ __align__(16)  float  g_bias[2][G4];
__device__ __align__(256) __half g_projW[(size_t)HID * TOT];
__device__ __align__(256) __half g_flat[(size_t)BDIM * TOT];
__device__ __align__(256) float  g_c[2][(size_t)BDIM * LHH];
__device__ __align__(256) float  g_y[(size_t)BDIM * HID];

// ---------------- generic helpers ----------------
__device__ __forceinline__ void cp16(void* smem, const void* gmem) {
    uint32_t s = (uint32_t)__cvta_generic_to_shared(smem);
    asm volatile("cp.async.cg.shared.global [%0], [%1], 16;\n" ::"r"(s), "l"(gmem));
}
__device__ __forceinline__ void cp16s(uint32_t s, const void* gmem) {
    asm volatile("cp.async.cg.shared.global [%0], [%1], 16;\n" ::"r"(s), "l"(gmem));
}
__device__ __forceinline__ void cp_commit() { asm volatile("cp.async.commit_group;\n"); }
template <int N>
__device__ __forceinline__ void cp_wait() { asm volatile("cp.async.wait_group %0;\n" ::"n"(N)); }

__device__ __forceinline__ float tanha(float x) {
    float y; asm("tanh.approx.f32 %0, %1;" : "=f"(y) : "f"(x)); return y;
}
__device__ __forceinline__ float sigt(float x) { return 0.5f * tanha(0.5f * x) + 0.5f; }

#ifdef TC_OK
__device__ __forceinline__ void mbar_init(uint32_t mbar, uint32_t cnt) {
    asm volatile("mbarrier.init.shared.b64 [%0], %1;" ::"r"(mbar), "r"(cnt) : "memory");
}
__device__ __forceinline__ void mbar_wait(uint32_t mbar, uint32_t parity) {
    asm volatile(
        "{\n\t.reg .pred P;\n\t"
        "WL%=:\n\t"
        "mbarrier.try_wait.parity.acquire.cta.shared::cta.b64 P, [%0], %1, 0x989680;\n\t"
        "@P bra WD%=;\n\t"
        "bra WL%=;\n\t"
        "WD%=:\n\t}" ::"r"(mbar), "r"(parity) : "memory");
}
__device__ __forceinline__ void mbar_wait_cl(uint32_t mbar, uint32_t parity) {
    asm volatile(
        "{\n\t.reg .pred P;\n\t"
        "WL%=:\n\t"
        "mbarrier.try_wait.parity.acquire.cluster.shared::cta.b64 P, [%0], %1, 0x989680;\n\t"
        "@P bra WD%=;\n\t"
        "bra WL%=;\n\t"
        "WD%=:\n\t}" ::"r"(mbar), "r"(parity) : "memory");
}
__device__ __forceinline__ void arrive_rank0(uint32_t mbar) {
    asm volatile(
        "{\n\t.reg .b32 ra;\n\t"
        "mapa.shared::cluster.u32 ra, %0, %1;\n\t"
        "mbarrier.arrive.shared::cluster.b64 _, [ra];\n\t}"
        ::"r"(mbar), "r"(0u) : "memory");
}
__device__ __forceinline__ void mma_f16_cg2(uint32_t d, uint64_t a, uint64_t b,
                                            uint32_t idesc, uint32_t en) {
    asm volatile(
        "{\n\t.reg .pred p;\n\tsetp.ne.u32 p, %4, 0;\n\t"
        "tcgen05.mma.cta_group::2.kind::f16 [%0], %1, %2, %3, {%5,%5,%5,%5,%5,%5,%5,%5}, p;\n\t}"
        ::"r"(d), "l"(a), "l"(b), "r"(idesc), "r"(en), "r"(0u) : "memory");
}
__device__ __forceinline__ void commit_mc_cg2(uint32_t mbar) {
    asm volatile(
        "tcgen05.commit.cta_group::2.mbarrier::arrive::one.shared::cluster.multicast::cluster.b64 [%0], %1;"
        ::"r"(mbar), "h"((uint16_t)3) : "memory");
}
__device__ __forceinline__ void cluster_sync() {
    asm volatile("barrier.cluster.arrive.aligned;" ::: "memory");
    asm volatile("barrier.cluster.wait.aligned;" ::: "memory");
}
#define LDTM_X32(r, addr)                                                                  \
    asm volatile(                                                                          \
        "tcgen05.ld.sync.aligned.32x32b.x32.b32 "                                          \
        "{%0,%1,%2,%3,%4,%5,%6,%7,%8,%9,%10,%11,%12,%13,%14,%15,"                          \
        "%16,%17,%18,%19,%20,%21,%22,%23,%24,%25,%26,%27,%28,%29,%30,%31}, [%32];"        \
        : "=r"((r)[0]), "=r"((r)[1]), "=r"((r)[2]), "=r"((r)[3]), "=r"((r)[4]),            \
          "=r"((r)[5]), "=r"((r)[6]), "=r"((r)[7]), "=r"((r)[8]), "=r"((r)[9]),            \
          "=r"((r)[10]), "=r"((r)[11]), "=r"((r)[12]), "=r"((r)[13]), "=r"((r)[14]),       \
          "=r"((r)[15]), "=r"((r)[16]), "=r"((r)[17]), "=r"((r)[18]), "=r"((r)[19]),       \
          "=r"((r)[20]), "=r"((r)[21]), "=r"((r)[22]), "=r"((r)[23]), "=r"((r)[24]),       \
          "=r"((r)[25]), "=r"((r)[26]), "=r"((r)[27]), "=r"((r)[28]), "=r"((r)[29]),       \
          "=r"((r)[30]), "=r"((r)[31])                                                     \
        : "r"(addr))
__device__ __forceinline__ void tc_wait_ld() {
    asm volatile("tcgen05.wait::ld.sync.aligned;" ::: "memory");
}
#endif  // TC_OK

// ---------------- big GEMM: cluster(2,1,1), pair tile 256x256, K-major fp16 ----------
// grid (2, n_tiles, m_pairs). mode 0: A=g_Xh,K=1024 -> g_G half. mode 1: A=g_flat,K=2048 -> g_y float+bias.
#define SMEM_BYTES 101376

__global__ void __launch_bounds__(256, 1) k_tcgemm(int mode, const float* __restrict__ bias) {
    extern __shared__ char dsm[];
    uint32_t smraw = (uint32_t)__cvta_generic_to_shared(dsm);
    uint32_t smb = (smraw + 1023) & ~1023u;
    char* base = dsm + (smb - smraw);

    const int tid = threadIdx.x, lane = tid & 31, wid = tid >> 5;
    const int rank = blockIdx.x & 1;

    const __half* A;
    const __half* B;
    int K;
    if (mode == 0) { A = g_Xh;   B = g_Wc;    K = CH;  }
    else           { A = g_flat; B = g_projW; K = TOT; }

    const size_t rowC = ((size_t)blockIdx.z * 2 + rank) * 128;  // this CTA's 128 rows
    const int n0 = blockIdx.y * 256;
    const __half* Ag = A + rowC * K;

#ifdef TC_OK
    // ============== cg2 tcgen05 path ==============
    const __half* Bg = B + (size_t)(n0 + rank * 128) * K;   // this CTA's 128 B-rows
    const uint32_t smA0 = smb + 1024;
    const uint32_t smB0 = smA0 + 16384;
    const uint32_t smA1 = smB0 + 16384;
    const uint32_t smB1 = smA1 + 16384;
    const uint32_t fullb[2] = {smb + 8,  smb + 16};   // count 2 (rank0's used)
    const uint32_t doneb[2] = {smb + 24, smb + 32};   // count 1, multicast commit
    const int NT = K / 64;

    if (wid == 0) {
        asm volatile("tcgen05.alloc.cta_group::2.sync.aligned.shared::cta.b32 [%0], %1;"
                     ::"r"(smb), "r"(256u) : "memory");
        asm volatile("tcgen05.relinquish_alloc_permit.cta_group::2.sync.aligned;" ::: "memory");
    }
    if (tid == 0) {
        mbar_init(fullb[0], 2); mbar_init(fullb[1], 2);
        mbar_init(doneb[0], 1); mbar_init(doneb[1], 1);
    }
    __syncthreads();
    uint32_t tmem;
    asm volatile("ld.shared.b32 %0, [%1];" : "=r"(tmem) : "r"(smb));
    cluster_sync();

    constexpr uint32_t IDESC = (1u << 4) | ((256 / 8) << 17) | ((256 / 16) << 24);
    const uint64_t DBASE = (2ull << 61) | (1ull << 46) | (64ull << 32) | (1ull << 16);

    auto prefetch = [&](int kc, uint32_t sa, uint32_t sb) {
        const __half* Ab = Ag + kc * 64;
#pragma unroll
        for (int it = 0; it < 4; it++) {
            int o = tid + it * 256;
            int r = o >> 3, seg = o & 7;
            uint32_t off = (uint32_t)(r * 128 + seg * 16);
            cp16s(sa + (off ^ ((off >> 3) & 0x70)), Ab + (size_t)r * K + seg * 8);
        }
        const __half* Bb = Bg + kc * 64;
#pragma unroll
        for (int it = 0; it < 4; it++) {
            int o = tid + it * 256;
            int r = o >> 3, seg = o & 7;
            uint32_t off = (uint32_t)(r * 128 + seg * 16);
            cp16s(sb + (off ^ ((off >> 3) & 0x70)), Bb + (size_t)r * K + seg * 8);
        }
        cp_commit();
    };

    prefetch(0, smA0, smB0);
    int phd0 = 0, phd1 = 0, phf0 = 0, phf1 = 0;

    for (int i = 0; i < NT; i++) {
        const int b = i & 1;
        if (i + 1 < NT) {
            const int bb = (i + 1) & 1;
            if (i >= 1) {
                if (bb) { mbar_wait(doneb[1], (uint32_t)phd1); phd1 ^= 1; }
                else    { mbar_wait(doneb[0], (uint32_t)phd0); phd0 ^= 1; }
            }
            prefetch(i + 1, bb ? smA1 : smA0, bb ? smB1 : smB0);
            cp_wait<1>();
        } else {
            cp_wait<0>();
        }
        __syncthreads();
        if (tid == 0) {
            asm volatile("fence.proxy.async;" ::: "memory");
            arrive_rank0(fullb[b]);
            if (rank == 0) {
                if (b) { mbar_wait_cl(fullb[1], (uint32_t)phf1); phf1 ^= 1; }
                else   { mbar_wait_cl(fullb[0], (uint32_t)phf0); phf0 ^= 1; }
                uint64_t da = DBASE | (((uint64_t)((b ? smA1 : smA0) >> 4)) & 0x3FFF);
                uint64_t db = DBASE | (((uint64_t)((b ? smB1 : smB0) >> 4)) & 0x3FFF);
#pragma unroll
                for (int s = 0; s < 4; s++)
                    mma_f16_cg2(tmem, da + s * 2, db + s * 2, IDESC, (i > 0 || s > 0) ? 1u : 0u);
                commit_mc_cg2(doneb[b]);
            }
        }
    }
    {
        const int lb = (NT - 1) & 1;
        if (lb) mbar_wait(doneb[1], (uint32_t)phd1);
        else    mbar_wait(doneb[0], (uint32_t)phd0);
    }
    asm volatile("tcgen05.fence::after_thread_sync;" ::: "memory");
    __syncthreads();

    // -------- epilogue: this CTA's 128 rows x 256 cols from its own TMEM --------
    uint32_t r[32];
    const int myrow = wid * 32 + lane;
    if (mode == 0) {
        __half* sO = (__half*)(base + 1024);  // [128][258]
        if (wid < 4) {
#pragma unroll
            for (int g = 0; g < 8; g++) {
                LDTM_X32(r, tmem + g * 32);
                tc_wait_ld();
#pragma unroll
                for (int c = 0; c < 32; c += 2) {
                    __half2 h = __floats2half2_rn(__uint_as_float(r[c]), __uint_as_float(r[c + 1]));
                    *(__half2*)&sO[myrow * 258 + g * 32 + c] = h;
                }
            }
        }
        __syncthreads();
#pragma unroll 4
        for (int it = 0; it < 64; it++) {
            int idx = tid + it * 256;
            int cp = idx & 127, row = idx >> 7;
            __half2 v = *(__half2*)&sO[row * 258 + cp * 2];
            *(__half2*)&g_G[(rowC + row) * TOT + n0 + cp * 2] = v;
        }
    } else {
        float* sF = (float*)(base + 1024);    // [128][129]
#pragma unroll
        for (int p = 0; p < 2; p++) {
            if (wid < 4) {
#pragma unroll
                for (int g = 0; g < 4; g++) {
                    LDTM_X32(r, tmem + p * 128 + g * 32);
                    tc_wait_ld();
#pragma unroll
                    for (int c = 0; c < 32; c++)
                        sF[myrow * 129 + g * 32 + c] = __uint_as_float(r[c]);
                }
            }
            __syncthreads();
#pragma unroll 4
            for (int it = 0; it < 64; it++) {
                int idx = tid + it * 256;
                int col = idx & 127, row = idx >> 7;
                int gc = n0 + p * 128 + col;
                g_y[(rowC + row) * HID + gc] = sF[row * 129 + col] + bias[gc];
            }
            __syncthreads();
        }
    }
    __syncthreads();
    cluster_sync();
    if (wid == 0) {
        asm volatile("tcgen05.dealloc.cta_group::2.sync.aligned.b32 %0, %1;"
                     ::"r"(tmem), "r"(256u));
    }
    cluster_sync();
#else
    // ============== HMMA fallback: per-CTA 128x256, full B ==============
    (void)base;
    const __half* Bg = B + (size_t)n0 * K;
    constexpr int SKH = 40;
    constexpr int STG = (128 + 256) * SKH * 2;
    const uint32_t sA_[3] = {smb, smb + STG, smb + 2 * STG};

    float acc[128];
#pragma unroll
    for (int i = 0; i < 128; i++) acc[i] = 0.f;

    const int wm = (wid & 1) * 64;
    const int wn = (wid >> 1) * 64;
    const int KT = K / 32;

    auto issue = [&](int kt, int s) {
        const uint32_t sa = sA_[s];
        const uint32_t sb = sA_[s] + 128 * SKH * 2;
        const __half* Ab = Ag + kt * 32;
#pragma unroll
        for (int i = 0; i < 2; i++) {
            int o = tid + i * 256;
            int rr = o >> 2, c = o & 3;
            cp16s(sa + rr * (SKH * 2) + c * 16, Ab + (size_t)rr * K + c * 8);
        }
        const __half* Bb = Bg + kt * 32;
#pragma unroll
        for (int i = 0; i < 4; i++) {
            int o = tid + i * 256;
            int rr = o >> 2, c = o & 3;
            cp16s(sb + rr * (SKH * 2) + c * 16, Bb + (size_t)rr * K + c * 8);
        }
        cp_commit();
    };

    issue(0, 0);
    if (KT > 1) issue(1, 1);
    if (KT > 2) issue(2, 2);

    for (int kt = 0; kt < KT; kt++) {
        const int rem = KT - 1 - kt;
        if (rem >= 2)      cp_wait<2>();
        else if (rem == 1) cp_wait<1>();
        else               cp_wait<0>();
        __syncthreads();

        const __half* cA = (const __half*)(dsm + (sA_[kt % 3] - smraw));
        const __half* cB = cA + 128 * SKH;
#pragma unroll
        for (int kk = 0; kk < 2; kk++) {
            const int kb = kk * 16 + (lane & 3) * 2;
            uint32_t afr[4][4], bfr[8][2];
#pragma unroll
            for (int mf = 0; mf < 4; mf++) {
                int rr = wm + mf * 16 + (lane >> 2);
                afr[mf][0] = *(const uint32_t*)(cA + rr * SKH + kb);
                afr[mf][1] = *(const uint32_t*)(cA + (rr + 8) * SKH + kb);
                afr[mf][2] = *(const uint32_t*)(cA + rr * SKH + kb + 8);
                afr[mf][3] = *(const uint32_t*)(cA + (rr + 8) * SKH + kb + 8);
            }
#pragma unroll
            for (int nf = 0; nf < 8; nf++) {
                int n = wn + nf * 8 + (lane >> 2);
                bfr[nf][0] = *(const uint32_t*)(cB + n * SKH + kb);
                bfr[nf][1] = *(const uint32_t*)(cB + n * SKH + kb + 8);
            }
#pragma unroll
            for (int mf = 0; mf < 4; mf++)
#pragma unroll
                for (int nf = 0; nf < 8; nf++) {
                    float* c = &acc[(mf * 8 + nf) * 4];
                    asm volatile(
                        "mma.sync.aligned.m16n8k16.row.col.f32.f16.f16.f32 "
                        "{%0,%1,%2,%3},{%4,%5,%6,%7},{%8,%9},{%0,%1,%2,%3};\n"
                        : "+f"(c[0]), "+f"(c[1]), "+f"(c[2]), "+f"(c[3])
                        : "r"(afr[mf][0]), "r"(afr[mf][1]), "r"(afr[mf][2]), "r"(afr[mf][3]),
                          "r"(bfr[nf][0]), "r"(bfr[nf][1]));
                }
        }
        __syncthreads();
        if (kt + 3 < KT) issue(kt + 3, (kt + 3) % 3);
    }

    if (mode == 0) {
#pragma unroll
        for (int mf = 0; mf < 4; mf++)
#pragma unroll
            for (int nf = 0; nf < 8; nf++) {
                const float* c = &acc[(mf * 8 + nf) * 4];
                int rr = wm + mf * 16 + (lane >> 2);
                int n = n0 + wn + nf * 8 + (lane & 3) * 2;
                __half2 h0 = __floats2half2_rn(c[0], c[1]);
                __half2 h1 = __floats2half2_rn(c[2], c[3]);
                *(__half2*)&g_G[(rowC + rr) * TOT + n]     = h0;
                *(__half2*)&g_G[(rowC + rr + 8) * TOT + n] = h1;
            }
    } else {
#pragma unroll
        for (int mf = 0; mf < 4; mf++)
#pragma unroll
            for (int nf = 0; nf < 8; nf++) {
                const float* c = &acc[(mf * 8 + nf) * 4];
                int rr = wm + mf * 16 + (lane >> 2);
                int n = n0 + wn + nf * 8 + (lane & 3) * 2;
                float b0 = bias[n], b1 = bias[n + 1];
                *(float2*)&g_y[(rowC + rr) * HID + n]     = make_float2(c[0] + b0, c[1] + b1);
                *(float2*)&g_y[(rowC + rr + 8) * HID + n] = make_float2(c[2] + b0, c[3] + b1);
            }
    }
#endif
}

// ---------------- HMMA core for the small recurrent GEMM ----------------
template <int BM, int BN, int WROWS, int WCOLS>
__device__ __forceinline__ void gemm_core(
    const __half* __restrict__ Aptr, int lda,
    const __half* __restrict__ Bptr, int ldb,
    int K, __half* sA, __half* sB, float* acc)
{
    constexpr int BK = 32, SK = 40;
    constexpr int THREADS = WROWS * WCOLS * 32;
    constexpr int WM = BM / WROWS, WN = BN / WCOLS;
    constexpr int MF = WM / 16, NF = WN / 8;

    const int tid  = threadIdx.x;
    const int lane = tid & 31, warp = tid >> 5;
    const int wm = (warp % WROWS) * WM;
    const int wn = (warp / WROWS) * WN;
    const int KT = K / BK;

    auto issue = [&](int kt, int buf) {
        const __half* Ag = Aptr + kt * BK;
#pragma unroll
        for (int i = 0; i < (BM * 4) / THREADS; i++) {
            int c = tid + i * THREADS;
            int r = c >> 2, kc = c & 3;
            cp16(sA + buf * (BM * SK) + r * SK + kc * 8, Ag + (size_t)r * lda + kc * 8);
        }
        const __half* Bg = Bptr + kt * BK;
#pragma unroll
        for (int i = 0; i < (BN * 4) / THREADS; i++) {
            int c = tid + i * THREADS;
            int r = c >> 2, kc = c & 3;
            cp16(sB + buf * (BN * SK) + r * SK + kc * 8, Bg + (size_t)r * ldb + kc * 8);
        }
        cp_commit();
    };

    issue(0, 0);
    for (int kt = 0; kt < KT; kt++) {
        if (kt + 1 < KT) { issue(kt + 1, (kt + 1) & 1); cp_wait<1>(); }
        else             { cp_wait<0>(); }
        __syncthreads();
        const __half* cA = sA + (kt & 1) * (BM * SK);
        const __half* cB = sB + (kt & 1) * (BN * SK);
#pragma unroll
        for (int kk = 0; kk < 2; kk++) {
            uint32_t afr[MF][4], bfr[NF][2];
            const int kb = kk * 16 + (lane & 3) * 2;
#pragma unroll
            for (int mf = 0; mf < MF; mf++) {
                int rr = wm + mf * 16 + (lane >> 2);
                afr[mf][0] = *(const uint32_t*)(cA + rr * SK + kb);
                afr[mf][1] = *(const uint32_t*)(cA + (rr + 8) * SK + kb);
                afr[mf][2] = *(const uint32_t*)(cA + rr * SK + kb + 8);
                afr[mf][3] = *(const uint32_t*)(cA + (rr + 8) * SK + kb + 8);
            }
#pragma unroll
            for (int nf = 0; nf < NF; nf++) {
                int n = wn + nf * 8 + (lane >> 2);
                bfr[nf][0] = *(const uint32_t*)(cB + n * SK + kb);
                bfr[nf][1] = *(const uint32_t*)(cB + n * SK + kb + 8);
            }
#pragma unroll
            for (int mf = 0; mf < MF; mf++)
#pragma unroll
                for (int nf = 0; nf < NF; nf++) {
                    float* c = &acc[((mf * NF) + nf) * 4];
                    asm volatile(
                        "mma.sync.aligned.m16n8k16.row.col.f32.f16.f16.f32 "
                        "{%0,%1,%2,%3},{%4,%5,%6,%7},{%8,%9},{%0,%1,%2,%3};\n"
                        : "+f"(c[0]), "+f"(c[1]), "+f"(c[2]), "+f"(c[3])
                        : "r"(afr[mf][0]), "r"(afr[mf][1]), "r"(afr[mf][2]), "r"(afr[mf][3]),
                          "r"(bfr[nf][0]), "r"(bfr[nf][1]));
                }
        }
        __syncthreads();
    }
}

// ---------------- conversion kernels ----------------
__global__ void __launch_bounds__(256) k_cvt_x(const float4* __restrict__ x4) {
    uint2* o = (uint2*)g_Xh;
    const size_t n4 = (size_t)BT * CH / 4;
    for (size_t i = blockIdx.x * (size_t)blockDim.x + threadIdx.x; i < n4;
         i += (size_t)gridDim.x * blockDim.x) {
        float4 v = x4[i];
        __half2 a = __floats2half2_rn(v.x, v.y);
        __half2 b = __floats2half2_rn(v.z, v.w);
        o[i] = make_uint2(*(uint32_t*)&a, *(uint32_t*)&b);
    }
}

__global__ void __launch_bounds__(256) k_cvt_w(
    const float* __restrict__ Wih_f, const float* __restrict__ Whh_f,
    const float* __restrict__ bih_f, const float* __restrict__ bhh_f,
    const float* __restrict__ Wih_b, const float* __restrict__ Whh_b,
    const float* __restrict__ bih_b, const float* __restrict__ bhh_b,
    const float* __restrict__ projW)
{
    const int S0 = TOT * CH;
    const int S1 = 2 * G4 * LHH;
    const int S2 = 2 * G4;
    const int S3 = HID * TOT;
    const int total = S0 + S1 + S2 + S3;
    for (int idx = blockIdx.x * blockDim.x + threadIdx.x; idx < total;
         idx += gridDim.x * blockDim.x) {
        if (idx < S0) {
            int p = idx >> 10, k = idx & 1023;
            int dir = p >> 10, q = p & 1023;
            int j = q >> 2, gi = q & 3;
            const float* W = dir ? Wih_b : Wih_f;
            g_Wc[idx] = __float2half_rn(W[(gi * LHH + j) * CH + k]);
        } else if (idx < S0 + S1) {
            int i = idx - S0;
            int dir = (i >= G4 * LHH);
            int ii = i - dir * (G4 * LHH);
            int p = ii >> 8, k = ii & 255;
            int j = p >> 2, gi = p & 3;
            const float* W = dir ? Whh_b : Whh_f;
            g_Whh[dir][p * LHH + k] = __float2half_rn(W[(gi * LHH + j) * LHH + k]);
        } else if (idx < S0 + S1 + S2) {
            int i = idx - S0 - S1;
            int dir = (i >= G4);
            int p = i - dir * G4;
            int j = p >> 2, gi = p & 3;
            const float* b1 = dir ? bih_b : bih_f;
            const float* b2 = dir ? bhh_b : bhh_f;
            g_bias[dir][p] = b1[gi * LHH + j] + b2[gi * LHH + j];
        } else {
            int i = idx - S0 - S1 - S2;
            g_projW[i] = __float2half_rn(projW[i]);
        }
    }
}

// ---------------- LSTM step 0: pure elementwise (c0 = 0) ----------------
__global__ void __launch_bounds__(256) k_lstm0() {
    int idx = blockIdx.x * 256 + threadIdx.x;
    int j = idx & 255;
    int dir = (idx >> 8) & 1;
    size_t row = (size_t)(idx >> 9);
    int t = dir ? (TS - 1) : 0;

    const __half* Gp = g_G + ((row * TS + t) * TOT + dir * G4 + j * 4);
    uint2 gw = *(const uint2*)Gp;
    __half2 g01 = *(__half2*)&gw.x;
    __half2 g23 = *(__half2*)&gw.y;
    float4 bb = *(const float4*)&g_bias[dir][j * 4];

    float gi = __low2float(g01)  + bb.x;
    float gg = __low2float(g23)  + bb.z;
    float go = __high2float(g23) + bb.w;

    float c_new = sigt(gi) * tanha(gg);
    float h = sigt(go) * tanha(c_new);
    g_c[dir][row * LHH + j] = c_new;
    g_flat[row * TOT + t * 512 + dir * 256 + j] = __float2half_rn(h);
}

// ---------------- LSTM steps 1..3: recurrent GEMM + cell (round-8 proven) ----------------
__global__ void __launch_bounds__(256) k_lstm(int step) {
    __shared__ __align__(16) char smraw[64 * 132 * 4];
    __half* sA = (__half*)smraw;
    __half* sB = (__half*)(smraw + 10240);
    float*  sG = (float*)smraw;

    const int dir  = blockIdx.z;
    const int tcur = dir ? (TS - 1 - step) : step;
    const int tprev = dir ? (tcur + 1) : (tcur - 1);

    float acc[32];
#pragma unroll
    for (int i = 0; i < 32; i++) acc[i] = 0.f;

    {
        const __half* A  = g_flat + (size_t)blockIdx.y * 64 * TOT + tprev * 512 + dir * 256;
        const __half* Bm = g_Whh[dir] + (size_t)blockIdx.x * 128 * LHH;
        gemm_core<64, 128, 2, 4>(A, TOT, Bm, LHH, LHH, sA, sB, acc);
    }
    __syncthreads();

    const int lane = threadIdx.x & 31, warp = threadIdx.x >> 5;
    const int wm = (warp % 2) * 32, wn = (warp / 2) * 32;
#pragma unroll
    for (int mf = 0; mf < 2; mf++)
#pragma unroll
        for (int nf = 0; nf < 4; nf++) {
            const float* c = &acc[(mf * 4 + nf) * 4];
            int rr = wm + mf * 16 + (lane >> 2);
            int n = wn + nf * 8 + (lane & 3) * 2;
            sG[rr * 132 + n]           = c[0];
            sG[rr * 132 + n + 1]       = c[1];
            sG[(rr + 8) * 132 + n]     = c[2];
            sG[(rr + 8) * 132 + n + 1] = c[3];
        }
    __syncthreads();

    const size_t row0 = (size_t)blockIdx.y * 64;
    const int n0 = blockIdx.x * 128;
#pragma unroll
    for (int it = 0; it < 8; it++) {
        int item = threadIdx.x + it * 256;
        int m = item >> 5, jl = item & 31;
        size_t rb = row0 + m;
        int j = (n0 >> 2) + jl;

        float4 gsum = *(float4*)&sG[m * 132 + jl * 4];
        const __half* Gp = g_G + ((rb * TS + tcur) * TOT + dir * G4 + n0 + jl * 4);
        uint2 gw = *(const uint2*)Gp;
        __half2 g01 = *(__half2*)&gw.x;
        __half2 g23 = *(__half2*)&gw.y;
        float4 bb = *(const float4*)&g_bias[dir][n0 + jl * 4];

        float gi = gsum.x + __low2float(g01)  + bb.x;
        float gf = gsum.y + __high2float(g01) + bb.y;
        float gg = gsum.z + __low2float(g23)  + bb.z;
        float go = gsum.w + __high2float(g23) + bb.w;

        float c_old = g_c[dir][rb * LHH + j];
        float c_new = sigt(gf) * c_old + sigt(gi) * tanha(gg);
        float h = sigt(go) * tanha(c_new);
        g_c[dir][rb * LHH + j] = c_new;
        g_flat[rb * TOT + tcur * 512 + dir * 256 + j] = __float2half_rn(h);
    }
}

// ---------------- LayerNorm + exact GELU + residual ----------------
__global__ void __launch_bounds__(512) k_ln(
    const float* __restrict__ x, const float* __restrict__ lng,
    const float* __restrict__ lnb, float* __restrict__ out)
{
    const size_t row = blockIdx.x;
    const int t = threadIdx.x;
    const float4* y4 = (const float4*)(g_y + row * HID);
    float4 v0 = y4[t], v1 = y4[t + 512];

    float s = v0.x + v0.y + v0.z + v0.w + v1.x + v1.y + v1.z + v1.w;
    float q = v0.x * v0.x + v0.y * v0.y + v0.z * v0.z + v0.w * v0.w +
              v1.x * v1.x + v1.y * v1.y + v1.z * v1.z + v1.w * v1.w;

    __shared__ float rs[16], rq[16], stat[2];
#pragma unroll
    for (int o = 16; o; o >>= 1) {
        s += __shfl_xor_sync(0xffffffffu, s, o);
        q += __shfl_xor_sync(0xffffffffu, q, o);
    }
    const int wid = t >> 5, lane = t & 31;
    if (!lane) { rs[wid] = s; rq[wid] = q; }
    __syncthreads();
    if (t < 32) {
        float a  = (t < 16) ? rs[t] : 0.f;
        float b2 = (t < 16) ? rq[t] : 0.f;
#pragma unroll
        for (int o = 8; o; o >>= 1) {
            a  += __shfl_xor_sync(0xffffffffu, a, o);
            b2 += __shfl_xor_sync(0xffffffffu, b2, o);
        }
        if (!t) {
            float mu = a * (1.0f / HID);
            float var = b2 * (1.0f / HID) - mu * mu;
            stat[0] = mu;
            stat[1] = rsqrtf(var + 1e-5f);
        }
    }
    __syncthreads();
    const float mu = stat[0], rstd = stat[1];

    const float4* x4 = (const float4*)(x + row * HID);
    const float4* g4 = (const float4*)lng;
    const float4* b4 = (const float4*)lnb;
    float4* o4 = (float4*)(out + row * HID);

    auto act = [&](float yv, float gg, float bb, float xv) {
        float u = (yv - mu) * rstd * gg + bb;
        return xv + 0.5f * u * (1.0f + erff(u * 0.70710678118f));
    };
#pragma unroll
    for (int half = 0; half < 2; half++) {
        int idx = t + half * 512;
        float4 v = half ? v1 : v0;
        float4 gg = g4[idx], bb = b4[idx], xx = x4[idx];
        float4 rr;
        rr.x = act(v.x, gg.x, bb.x, xx.x);
        rr.y = act(v.y, gg.y, bb.y, xx.y);
        rr.z = act(v.z, gg.z, bb.z, xx.z);
        rr.w = act(v.w, gg.w, bb.w, xx.w);
        o4[idx] = rr;
    }
}

// ---------------- launcher ----------------
static void launch_gemm(int mode, const float* bias, dim3 grid) {
    cudaLaunchConfig_t cfg = {};
    cfg.gridDim = grid;
    cfg.blockDim = dim3(256, 1, 1);
    cfg.dynamicSmemBytes = SMEM_BYTES;
    cfg.stream = 0;
    cudaLaunchAttribute at[1];
    at[0].id = cudaLaunchAttributeClusterDimension;
    at[0].val.clusterDim.x = 2;
    at[0].val.clusterDim.y = 1;
    at[0].val.clusterDim.z = 1;
    cfg.attrs = at;
    cfg.numAttrs = 1;
    cudaLaunchKernelEx(&cfg, k_tcgemm, mode, bias);
}

extern "C" void kernel_launch(void* const* d_in, const int* in_sizes, int n_in,
                              void* d_out, int out_size) {
    const float* x      = (const float*)d_in[0];
    const float* Wih_f  = (const float*)d_in[1];
    const float* Whh_f  = (const float*)d_in[2];
    const float* bih_f  = (const float*)d_in[3];
    const float* bhh_f  = (const float*)d_in[4];
    const float* Wih_b  = (const float*)d_in[5];
    const float* Whh_b  = (const float*)d_in[6];
    const float* bih_b  = (const float*)d_in[7];
    const float* bhh_b  = (const float*)d_in[8];
    const float* projW  = (const float*)d_in[9];
    const float* projb  = (const float*)d_in[10];
    const float* lng    = (const float*)d_in[11];
    const float* lnb    = (const float*)d_in[12];
    float* out = (float*)d_out;

    static bool attr_done = false;
    if (!attr_done) {
        cudaFuncSetAttribute(k_tcgemm, cudaFuncAttributeMaxDynamicSharedMemorySize, SMEM_BYTES);
        attr_done = true;
    }

    k_cvt_x<<<4096, 256>>>((const float4*)x);
    k_cvt_w<<<2048, 256>>>(Wih_f, Whh_f, bih_f, bhh_f, Wih_b, Whh_b, bih_b, bhh_b, projW);
    launch_gemm(0, nullptr, dim3(2, TOT / 256, BT / 256));
    k_lstm0<<<(BDIM * 512) / 256, 256>>>();
    for (int s = 1; s < TS; s++) k_lstm<<<dim3(8, 256, 2), 256>>>(s);
    launch_gemm(1, projb, dim3(2, HID / 256, BDIM / 256));
    k_ln<<<16384, 512>>>(x, lng, lnb, out);
}

// round 13
// speedup vs baseline: 1.3767x; 1.3767x over previous
#include <cuda_runtime.h>
#include <cuda_fp16.h>
#include <cstdint>

#define BDIM  16384
#define HID   4096
#define TS    4
#define CH    1024
#define LHH   256
#define G4    1024
#define TOT   2048
#define BT    65536

#if defined(__CUDA_ARCH__) && (defined(__CUDA_ARCH_FEAT_SM103_ALL) || defined(__CUDA_ARCH_FEAT_SM100_ALL))
#define TC_OK 1
#endif

// ---------------- scratch (device globals: allocation-free) ----------------
__device__ __align__(256) __half g_Xh[(size_t)BT * CH];
__device__ __align__(256) __half g_G[(size_t)BT * TOT];
__device__ __align__(256) __half g_Wc[TOT * CH];
__device__ __align__(256) __half g_Whh[2][G4 * LHH];
__device__ __align__(16)  float  g_bias[2][G4];
__device__ __align__(256) __half g_projW[(size_t)HID * TOT];
__device__ __align__(256) __half g_flat[(size_t)BDIM * TOT];
__device__ __align__(256) float  g_c[2][(size_t)BDIM * LHH];
__device__ __align__(256) float  g_y[(size_t)BDIM * HID];

// ---------------- generic helpers ----------------
__device__ __forceinline__ void cp16(void* smem, const void* gmem) {
    uint32_t s = (uint32_t)__cvta_generic_to_shared(smem);
    asm volatile("cp.async.cg.shared.global [%0], [%1], 16;\n" ::"r"(s), "l"(gmem));
}
__device__ __forceinline__ void cp16s(uint32_t s, const void* gmem) {
    asm volatile("cp.async.cg.shared.global [%0], [%1], 16;\n" ::"r"(s), "l"(gmem));
}
__device__ __forceinline__ void cp_commit() { asm volatile("cp.async.commit_group;\n"); }
template <int N>
__device__ __forceinline__ void cp_wait() { asm volatile("cp.async.wait_group %0;\n" ::"n"(N)); }

__device__ __forceinline__ float tanha(float x) {
    float y; asm("tanh.approx.f32 %0, %1;" : "=f"(y) : "f"(x)); return y;
}
__device__ __forceinline__ float sigt(float x) { return 0.5f * tanha(0.5f * x) + 0.5f; }

#ifdef TC_OK
__device__ __forceinline__ uint32_t elect1() {
    uint32_t p;
    asm volatile("{\n\t.reg .pred p;\n\telect.sync _|p, 0xFFFFFFFF;\n\tselp.b32 %0,1,0,p;\n\t}"
                 : "=r"(p));
    return p;
}
__device__ __forceinline__ void mbar_init(uint32_t mbar, uint32_t cnt) {
    asm volatile("mbarrier.init.shared.b64 [%0], %1;" ::"r"(mbar), "r"(cnt) : "memory");
}
__device__ __forceinline__ void mbar_wait(uint32_t mbar, uint32_t parity) {
    asm volatile(
        "{\n\t.reg .pred P;\n\t"
        "WL%=:\n\t"
        "mbarrier.try_wait.parity.acquire.cta.shared::cta.b64 P, [%0], %1, 0x989680;\n\t"
        "@P bra WD%=;\n\t"
        "bra WL%=;\n\t"
        "WD%=:\n\t}" ::"r"(mbar), "r"(parity) : "memory");
}
__device__ __forceinline__ void tc_commit(uint32_t mbar) {
    asm volatile(
        "tcgen05.commit.cta_group::1.mbarrier::arrive::one.shared::cluster.b64 [%0];"
        ::"r"(mbar) : "memory");
}
__device__ __forceinline__ void mma_f16_ss(uint32_t d, uint64_t a, uint64_t b,
                                           uint32_t idesc, uint32_t en) {
    asm volatile(
        "{\n\t.reg .pred p;\n\tsetp.ne.u32 p, %4, 0;\n\t"
        "tcgen05.mma.cta_group::1.kind::f16 [%0], %1, %2, %3, {%5,%5,%5,%5}, p;\n\t}"
        ::"r"(d), "l"(a), "l"(b), "r"(idesc), "r"(en), "r"(0u) : "memory");
}
#define LDTM_X32(r, addr)                                                                  \
    asm volatile(                                                                          \
        "tcgen05.ld.sync.aligned.32x32b.x32.b32 "                                          \
        "{%0,%1,%2,%3,%4,%5,%6,%7,%8,%9,%10,%11,%12,%13,%14,%15,"                          \
        "%16,%17,%18,%19,%20,%21,%22,%23,%24,%25,%26,%27,%28,%29,%30,%31}, [%32];"        \
        : "=r"((r)[0]), "=r"((r)[1]), "=r"((r)[2]), "=r"((r)[3]), "=r"((r)[4]),            \
          "=r"((r)[5]), "=r"((r)[6]), "=r"((r)[7]), "=r"((r)[8]), "=r"((r)[9]),            \
          "=r"((r)[10]), "=r"((r)[11]), "=r"((r)[12]), "=r"((r)[13]), "=r"((r)[14]),       \
          "=r"((r)[15]), "=r"((r)[16]), "=r"((r)[17]), "=r"((r)[18]), "=r"((r)[19]),       \
          "=r"((r)[20]), "=r"((r)[21]), "=r"((r)[22]), "=r"((r)[23]), "=r"((r)[24]),       \
          "=r"((r)[25]), "=r"((r)[26]), "=r"((r)[27]), "=r"((r)[28]), "=r"((r)[29]),       \
          "=r"((r)[30]), "=r"((r)[31])                                                     \
        : "r"(addr))
__device__ __forceinline__ void tc_wait_ld() {
    asm volatile("tcgen05.wait::ld.sync.aligned;" ::: "memory");
}
#endif  // TC_OK

// ---------------- big GEMM kernel: C tiles of 128 x 256, K-major fp16 (round-8) --------
#define TCM 128
#define TCN 256
#define SMEM_BYTES 101376

__global__ void __launch_bounds__(256, 1) k_tcgemm(int mode, const float* __restrict__ bias) {
    extern __shared__ char dsm[];
    uint32_t smraw = (uint32_t)__cvta_generic_to_shared(dsm);
    uint32_t smb = (smraw + 1023) & ~1023u;
    char* base = dsm + (smb - smraw);

    const int tid = threadIdx.x, lane = tid & 31, wid = tid >> 5;

    const __half* A;
    const __half* B;
    int K;
    if (mode == 0) { A = g_Xh;   B = g_Wc;    K = CH;  }
    else           { A = g_flat; B = g_projW; K = TOT; }

    const size_t row0 = (size_t)blockIdx.y * TCM;
    const int n0 = blockIdx.x * TCN;
    const __half* Ag = A + row0 * K;
    const __half* Bg = B + (size_t)n0 * K;

#ifdef TC_OK
    const uint32_t smA0 = smb + 1024;
    const uint32_t smA1 = smA0 + 16384;
    const uint32_t smB0 = smA1 + 16384;
    const uint32_t smB1 = smB0 + 32768;
    const uint32_t mbar0 = smb + 8, mbar1 = smb + 16;
    const int NT = K / 64;

    if (wid == 0) {
        asm volatile("tcgen05.alloc.cta_group::1.sync.aligned.shared::cta.b32 [%0], %1;"
                     ::"r"(smb), "r"(256u) : "memory");
        asm volatile("tcgen05.relinquish_alloc_permit.cta_group::1.sync.aligned;" ::: "memory");
    }
    if (tid == 0) { mbar_init(mbar0, 1); mbar_init(mbar1, 1); }
    __syncthreads();
    uint32_t tmem;
    asm volatile("ld.shared.b32 %0, [%1];" : "=r"(tmem) : "r"(smb));

    const uint32_t el = (wid == 0) ? elect1() : 0u;
    constexpr uint32_t IDESC = (1u << 4) | ((TCN / 8) << 17) | ((TCM / 16) << 24);
    const uint64_t DBASE = (2ull << 61) | (1ull << 46) | (64ull << 32) | (1ull << 16);

    auto prefetch = [&](int kc, uint32_t sa, uint32_t sb) {
        const __half* Ab = Ag + kc * 64;
#pragma unroll
        for (int it = 0; it < 4; it++) {
            int o = tid + it * 256;
            int r = o >> 3, seg = o & 7;
            uint32_t off = (uint32_t)(r * 128 + seg * 16);
            cp16s(sa + (off ^ ((off >> 3) & 0x70)), Ab + (size_t)r * K + seg * 8);
        }
        const __half* Bb = Bg + kc * 64;
#pragma unroll
        for (int it = 0; it < 8; it++) {
            int o = tid + it * 256;
            int r = o >> 3, seg = o & 7;
            uint32_t off = (uint32_t)(r * 128 + seg * 16);
            cp16s(sb + (off ^ ((off >> 3) & 0x70)), Bb + (size_t)r * K + seg * 8);
        }
        cp_commit();
    };

    prefetch(0, smA0, smB0);
    int ph0 = 0, ph1 = 0;

    for (int i = 0; i < NT; i++) {
        const int b = i & 1;
        if (i + 1 < NT) {
            const int bb = (i + 1) & 1;
            if (i >= 1) {
                if (bb) { mbar_wait(mbar1, (uint32_t)ph1); ph1 ^= 1; }
                else    { mbar_wait(mbar0, (uint32_t)ph0); ph0 ^= 1; }
            }
            prefetch(i + 1, bb ? smA1 : smA0, bb ? smB1 : smB0);
            cp_wait<1>();
        } else {
            cp_wait<0>();
        }
        __syncthreads();
        if (wid == 0 && el) {
            asm volatile("fence.proxy.async.shared::cta;" ::: "memory");
            uint64_t da = DBASE | (((uint64_t)((b ? smA1 : smA0) >> 4)) & 0x3FFF);
            uint64_t db = DBASE | (((uint64_t)((b ? smB1 : smB0) >> 4)) & 0x3FFF);
#pragma unroll
            for (int s = 0; s < 4; s++)
                mma_f16_ss(tmem, da + s * 2, db + s * 2, IDESC, (i > 0 || s > 0) ? 1u : 0u);
            tc_commit(b ? mbar1 : mbar0);
        }
    }
    {
        const int lb = (NT - 1) & 1;
        if (lb) mbar_wait(mbar1, (uint32_t)ph1);
        else    mbar_wait(mbar0, (uint32_t)ph0);
    }
    asm volatile("tcgen05.fence::after_thread_sync;" ::: "memory");
    __syncthreads();

    uint32_t r[32];
    const int myrow = wid * 32 + lane;
    if (mode == 0) {
        __half* sO = (__half*)(base + 1024);  // [128][258]
        if (wid < 4) {
#pragma unroll
            for (int g = 0; g < 8; g++) {
                LDTM_X32(r, tmem + g * 32);
                tc_wait_ld();
#pragma unroll
                for (int c = 0; c < 32; c += 2) {
                    __half2 h = __floats2half2_rn(__uint_as_float(r[c]), __uint_as_float(r[c + 1]));
                    *(__half2*)&sO[myrow * 258 + g * 32 + c] = h;
                }
            }
        }
        __syncthreads();
#pragma unroll 4
        for (int it = 0; it < 64; it++) {
            int idx = tid + it * 256;
            int cp = idx & 127, row = idx >> 7;
            __half2 v = *(__half2*)&sO[row * 258 + cp * 2];
            *(__half2*)&g_G[(row0 + row) * TOT + n0 + cp * 2] = v;
        }
    } else {
        float* sF = (float*)(base + 1024);    // [128][129]
#pragma unroll
        for (int p = 0; p < 2; p++) {
            if (wid < 4) {
#pragma unroll
                for (int g = 0; g < 4; g++) {
                    LDTM_X32(r, tmem + p * 128 + g * 32);
                    tc_wait_ld();
#pragma unroll
                    for (int c = 0; c < 32; c++)
                        sF[myrow * 129 + g * 32 + c] = __uint_as_float(r[c]);
                }
            }
            __syncthreads();
#pragma unroll 4
            for (int it = 0; it < 64; it++) {
                int idx = tid + it * 256;
                int col = idx & 127, row = idx >> 7;
                int gc = n0 + p * 128 + col;
                g_y[(row0 + row) * HID + gc] = sF[row * 129 + col] + bias[gc];
            }
            __syncthreads();
        }
    }
    __syncthreads();
    if (wid == 0) {
        asm volatile("tcgen05.dealloc.cta_group::1.sync.aligned.b32 %0, %1;"
                     ::"r"(tmem), "r"(256u));
    }
#else
    // HMMA fallback (family cubin)
    (void)base;
    constexpr int SKH = 40;
    constexpr int STG = (TCM + TCN) * SKH * 2;
    const uint32_t sA_[3] = {smb, smb + STG, smb + 2 * STG};

    float acc[128];
#pragma unroll
    for (int i = 0; i < 128; i++) acc[i] = 0.f;

    const int wm = (wid & 1) * 64;
    const int wn = (wid >> 1) * 64;
    const int KT = K / 32;

    auto issue = [&](int kt, int s) {
        const uint32_t sa = sA_[s];
        const uint32_t sb = sA_[s] + TCM * SKH * 2;
        const __half* Ab = Ag + kt * 32;
#pragma unroll
        for (int i = 0; i < 2; i++) {
            int o = tid + i * 256;
            int rr = o >> 2, c = o & 3;
            cp16s(sa + rr * (SKH * 2) + c * 16, Ab + (size_t)rr * K + c * 8);
        }
        const __half* Bb = Bg + kt * 32;
#pragma unroll
        for (int i = 0; i < 4; i++) {
            int o = tid + i * 256;
            int rr = o >> 2, c = o & 3;
            cp16s(sb + rr * (SKH * 2) + c * 16, Bb + (size_t)rr * K + c * 8);
        }
        cp_commit();
    };

    issue(0, 0);
    if (KT > 1) issue(1, 1);
    if (KT > 2) issue(2, 2);

    for (int kt = 0; kt < KT; kt++) {
        const int rem = KT - 1 - kt;
        if (rem >= 2)      cp_wait<2>();
        else if (rem == 1) cp_wait<1>();
        else               cp_wait<0>();
        __syncthreads();

        const __half* cA = (const __half*)(dsm + (sA_[kt % 3] - smraw));
        const __half* cB = cA + TCM * SKH;
#pragma unroll
        for (int kk = 0; kk < 2; kk++) {
            const int kb = kk * 16 + (lane & 3) * 2;
            uint32_t afr[4][4], bfr[8][2];
#pragma unroll
            for (int mf = 0; mf < 4; mf++) {
                int rr = wm + mf * 16 + (lane >> 2);
                afr[mf][0] = *(const uint32_t*)(cA + rr * SKH + kb);
                afr[mf][1] = *(const uint32_t*)(cA + (rr + 8) * SKH + kb);
                afr[mf][2] = *(const uint32_t*)(cA + rr * SKH + kb + 8);
                afr[mf][3] = *(const uint32_t*)(cA + (rr + 8) * SKH + kb + 8);
            }
#pragma unroll
            for (int nf = 0; nf < 8; nf++) {
                int n = wn + nf * 8 + (lane >> 2);
                bfr[nf][0] = *(const uint32_t*)(cB + n * SKH + kb);
                bfr[nf][1] = *(const uint32_t*)(cB + n * SKH + kb + 8);
            }
#pragma unroll
            for (int mf = 0; mf < 4; mf++)
#pragma unroll
                for (int nf = 0; nf < 8; nf++) {
                    float* c = &acc[(mf * 8 + nf) * 4];
                    asm volatile(
                        "mma.sync.aligned.m16n8k16.row.col.f32.f16.f16.f32 "
                        "{%0,%1,%2,%3},{%4,%5,%6,%7},{%8,%9},{%0,%1,%2,%3};\n"
                        : "+f"(c[0]), "+f"(c[1]), "+f"(c[2]), "+f"(c[3])
                        : "r"(afr[mf][0]), "r"(afr[mf][1]), "r"(afr[mf][2]), "r"(afr[mf][3]),
                          "r"(bfr[nf][0]), "r"(bfr[nf][1]));
                }
        }
        __syncthreads();
        if (kt + 3 < KT) issue(kt + 3, (kt + 3) % 3);
    }

    if (mode == 0) {
#pragma unroll
        for (int mf = 0; mf < 4; mf++)
#pragma unroll
            for (int nf = 0; nf < 8; nf++) {
                const float* c = &acc[(mf * 8 + nf) * 4];
                int rr = wm + mf * 16 + (lane >> 2);
                int n = n0 + wn + nf * 8 + (lane & 3) * 2;
                __half2 h0 = __floats2half2_rn(c[0], c[1]);
                __half2 h1 = __floats2half2_rn(c[2], c[3]);
                *(__half2*)&g_G[(row0 + rr) * TOT + n]     = h0;
                *(__half2*)&g_G[(row0 + rr + 8) * TOT + n] = h1;
            }
    } else {
#pragma unroll
        for (int mf = 0; mf < 4; mf++)
#pragma unroll
            for (int nf = 0; nf < 8; nf++) {
                const float* c = &acc[(mf * 8 + nf) * 4];
                int rr = wm + mf * 16 + (lane >> 2);
                int n = n0 + wn + nf * 8 + (lane & 3) * 2;
                float b0 = bias[n], b1 = bias[n + 1];
                *(float2*)&g_y[(row0 + rr) * HID + n]     = make_float2(c[0] + b0, c[1] + b1);
                *(float2*)&g_y[(row0 + rr + 8) * HID + n] = make_float2(c[2] + b0, c[3] + b1);
            }
    }
#endif
}

// ---------------- 3-stage HMMA core for the recurrent GEMM ----------------
// Layout per stage: [BM rows A | BN rows B], SK=40 halves/row. STAGE=(BM+BN)*80 bytes.
template <int BM, int BN, int WROWS, int WCOLS>
__device__ __forceinline__ void gemm_core3(
    const __half* __restrict__ Aptr, int lda,
    const __half* __restrict__ Bptr, int ldb,
    int K, char* sm, float* acc)
{
    constexpr int BK = 32, SK = 40;
    constexpr int THREADS = WROWS * WCOLS * 32;
    constexpr int WM = BM / WROWS, WN = BN / WCOLS;
    constexpr int MF = WM / 16, NF = WN / 8;
    constexpr int STAGE = (BM + BN) * SK * 2;

    const int tid  = threadIdx.x;
    const int lane = tid & 31, warp = tid >> 5;
    const int wm = (warp % WROWS) * WM;
    const int wn = (warp / WROWS) * WN;
    const int KT = K / BK;

    auto issue = [&](int kt, int s) {
        __half* sA = (__half*)(sm + s * STAGE);
        __half* sB = sA + BM * SK;
        const __half* Ag = Aptr + kt * BK;
#pragma unroll
        for (int i = 0; i < (BM * 4) / THREADS; i++) {
            int c = tid + i * THREADS;
            int r = c >> 2, kc = c & 3;
            cp16(sA + r * SK + kc * 8, Ag + (size_t)r * lda + kc * 8);
        }
        const __half* Bg = Bptr + kt * BK;
#pragma unroll
        for (int i = 0; i < (BN * 4) / THREADS; i++) {
            int c = tid + i * THREADS;
            int r = c >> 2, kc = c & 3;
            cp16(sB + r * SK + kc * 8, Bg + (size_t)r * ldb + kc * 8);
        }
        cp_commit();
    };

    issue(0, 0);
    if (KT > 1) issue(1, 1);
    if (KT > 2) issue(2, 2);

    for (int kt = 0; kt < KT; kt++) {
        const int rem = KT - 1 - kt;
        if (rem >= 2)      cp_wait<2>();
        else if (rem == 1) cp_wait<1>();
        else               cp_wait<0>();
        __syncthreads();

        const __half* cA = (const __half*)(sm + (kt % 3) * STAGE);
        const __half* cB = cA + BM * SK;
#pragma unroll
        for (int kk = 0; kk < 2; kk++) {
            uint32_t afr[MF][4], bfr[NF][2];
            const int kb = kk * 16 + (lane & 3) * 2;
#pragma unroll
            for (int mf = 0; mf < MF; mf++) {
                int rr = wm + mf * 16 + (lane >> 2);
                afr[mf][0] = *(const uint32_t*)(cA + rr * SK + kb);
                afr[mf][1] = *(const uint32_t*)(cA + (rr + 8) * SK + kb);
                afr[mf][2] = *(const uint32_t*)(cA + rr * SK + kb + 8);
                afr[mf][3] = *(const uint32_t*)(cA + (rr + 8) * SK + kb + 8);
            }
#pragma unroll
            for (int nf = 0; nf < NF; nf++) {
                int n = wn + nf * 8 + (lane >> 2);
                bfr[nf][0] = *(const uint32_t*)(cB + n * SK + kb);
                bfr[nf][1] = *(const uint32_t*)(cB + n * SK + kb + 8);
            }
#pragma unroll
            for (int mf = 0; mf < MF; mf++)
#pragma unroll
                for (int nf = 0; nf < NF; nf++) {
                    float* c = &acc[((mf * NF) + nf) * 4];
                    asm volatile(
                        "mma.sync.aligned.m16n8k16.row.col.f32.f16.f16.f32 "
                        "{%0,%1,%2,%3},{%4,%5,%6,%7},{%8,%9},{%0,%1,%2,%3};\n"
                        : "+f"(c[0]), "+f"(c[1]), "+f"(c[2]), "+f"(c[3])
                        : "r"(afr[mf][0]), "r"(afr[mf][1]), "r"(afr[mf][2]), "r"(afr[mf][3]),
                          "r"(bfr[nf][0]), "r"(bfr[nf][1]));
                }
        }
        __syncthreads();
        if (kt + 3 < KT) issue(kt + 3, (kt + 3) % 3);
    }
}

// ---------------- merged conversion kernel (validated in rounds 5/6) ----------------
__global__ void __launch_bounds__(256) k_cvt(
    const float4* __restrict__ x4,
    const float* __restrict__ Wih_f, const float* __restrict__ Whh_f,
    const float* __restrict__ bih_f, const float* __restrict__ bhh_f,
    const float* __restrict__ Wih_b, const float* __restrict__ Whh_b,
    const float* __restrict__ bih_b, const float* __restrict__ bhh_b,
    const float* __restrict__ projW)
{
    const int S4 = (int)((size_t)BT * CH / 4);
    const int S0 = TOT * CH;
    const int S1 = 2 * G4 * LHH;
    const int S2 = 2 * G4;
    const int S3 = HID * TOT;
    const int total = S4 + S0 + S1 + S2 + S3;
    uint2* xo = (uint2*)g_Xh;
    for (int idx = blockIdx.x * blockDim.x + threadIdx.x; idx < total;
         idx += gridDim.x * blockDim.x) {
        if (idx < S4) {
            float4 v = x4[idx];
            __half2 a = __floats2half2_rn(v.x, v.y);
            __half2 b = __floats2half2_rn(v.z, v.w);
            xo[idx] = make_uint2(*(uint32_t*)&a, *(uint32_t*)&b);
        } else if (idx < S4 + S0) {
            int i = idx - S4;
            int p = i >> 10, k = i & 1023;
            int dir = p >> 10, q = p & 1023;
            int j = q >> 2, gi = q & 3;
            const float* W = dir ? Wih_b : Wih_f;
            g_Wc[i] = __float2half_rn(W[(gi * LHH + j) * CH + k]);
        } else if (idx < S4 + S0 + S1) {
            int i = idx - S4 - S0;
            int dir = (i >= G4 * LHH);
            int ii = i - dir * (G4 * LHH);
            int p = ii >> 8, k = ii & 255;
            int j = p >> 2, gi = p & 3;
            const float* W = dir ? Whh_b : Whh_f;
            g_Whh[dir][p * LHH + k] = __float2half_rn(W[(gi * LHH + j) * LHH + k]);
        } else if (idx < S4 + S0 + S1 + S2) {
            int i = idx - S4 - S0 - S1;
            int dir = (i >= G4);
            int p = i - dir * G4;
            int j = p >> 2, gi = p & 3;
            const float* b1 = dir ? bih_b : bih_f;
            const float* b2 = dir ? bhh_b : bhh_f;
            g_bias[dir][p] = b1[gi * LHH + j] + b2[gi * LHH + j];
        } else {
            int i = idx - S4 - S0 - S1 - S2;
            g_projW[i] = __float2half_rn(projW[i]);
        }
    }
}

// ---------------- LSTM step 0: pure elementwise (c0 = 0) ----------------
__global__ void __launch_bounds__(256) k_lstm0() {
    int idx = blockIdx.x * 256 + threadIdx.x;
    int j = idx & 255;
    int dir = (idx >> 8) & 1;
    size_t row = (size_t)(idx >> 9);
    int t = dir ? (TS - 1) : 0;

    const __half* Gp = g_G + ((row * TS + t) * TOT + dir * G4 + j * 4);
    uint2 gw = *(const uint2*)Gp;
    __half2 g01 = *(__half2*)&gw.x;
    __half2 g23 = *(__half2*)&gw.y;
    float4 bb = *(const float4*)&g_bias[dir][j * 4];

    float gi = __low2float(g01)  + bb.x;
    float gg = __low2float(g23)  + bb.z;
    float go = __high2float(g23) + bb.w;

    float c_new = sigt(gi) * tanha(gg);
    float h = sigt(go) * tanha(c_new);
    g_c[dir][row * LHH + j] = c_new;
    g_flat[row * TOT + t * 512 + dir * 256 + j] = __float2half_rn(h);
}

// ---------------- LSTM steps 1..3: recurrent GEMM (3-stage) + cell ----------------
__global__ void __launch_bounds__(256) k_lstm(int step) {
    __shared__ __align__(16) char smraw[3 * (64 + 128) * 40 * 2];  // 46080 B
    float* sG = (float*)smraw;

    const int dir  = blockIdx.z;
    const int tcur = dir ? (TS - 1 - step) : step;
    const int tprev = dir ? (tcur + 1) : (tcur - 1);

    float acc[32];
#pragma unroll
    for (int i = 0; i < 32; i++) acc[i] = 0.f;

    {
        const __half* A  = g_flat + (size_t)blockIdx.y * 64 * TOT + tprev * 512 + dir * 256;
        const __half* Bm = g_Whh[dir] + (size_t)blockIdx.x * 128 * LHH;
        gemm_core3<64, 128, 2, 4>(A, TOT, Bm, LHH, LHH, smraw, acc);
    }
    __syncthreads();

    const int lane = threadIdx.x & 31, warp = threadIdx.x >> 5;
    const int wm = (warp % 2) * 32, wn = (warp / 2) * 32;
#pragma unroll
    for (int mf = 0; mf < 2; mf++)
#pragma unroll
        for (int nf = 0; nf < 4; nf++) {
            const float* c = &acc[(mf * 4 + nf) * 4];
            int rr = wm + mf * 16 + (lane >> 2);
            int n = wn + nf * 8 + (lane & 3) * 2;
            sG[rr * 132 + n]           = c[0];
            sG[rr * 132 + n + 1]       = c[1];
            sG[(rr + 8) * 132 + n]     = c[2];
            sG[(rr + 8) * 132 + n + 1] = c[3];
        }
    __syncthreads();

    const size_t row0 = (size_t)blockIdx.y * 64;
    const int n0 = blockIdx.x * 128;
#pragma unroll
    for (int it = 0; it < 8; it++) {
        int item = threadIdx.x + it * 256;
        int m = item >> 5, jl = item & 31;
        size_t rb = row0 + m;
        int j = (n0 >> 2) + jl;

        float4 gsum = *(float4*)&sG[m * 132 + jl * 4];
        const __half* Gp = g_G + ((rb * TS + tcur) * TOT + dir * G4 + n0 + jl * 4);
        uint2 gw = *(const uint2*)Gp;
        __half2 g01 = *(__half2*)&gw.x;
        __half2 g23 = *(__half2*)&gw.y;
        float4 bb = *(const float4*)&g_bias[dir][n0 + jl * 4];

        float gi = gsum.x + __low2float(g01)  + bb.x;
        float gf = gsum.y + __high2float(g01) + bb.y;
        float gg = gsum.z + __low2float(g23)  + bb.z;
        float go = gsum.w + __high2float(g23) + bb.w;

        float c_old = g_c[dir][rb * LHH + j];
        float c_new = sigt(gf) * c_old + sigt(gi) * tanha(gg);
        float h = sigt(go) * tanha(c_new);
        g_c[dir][rb * LHH + j] = c_new;
        g_flat[rb * TOT + tcur * 512 + dir * 256 + j] = __float2half_rn(h);
    }
}

// ---------------- LayerNorm + exact GELU + residual ----------------
__global__ void __launch_bounds__(512) k_ln(
    const float* __restrict__ x, const float* __restrict__ lng,
    const float* __restrict__ lnb, float* __restrict__ out)
{
    const size_t row = blockIdx.x;
    const int t = threadIdx.x;
    const float4* y4 = (const float4*)(g_y + row * HID);
    float4 v0 = y4[t], v1 = y4[t + 512];

    float s = v0.x + v0.y + v0.z + v0.w + v1.x + v1.y + v1.z + v1.w;
    float q = v0.x * v0.x + v0.y * v0.y + v0.z * v0.z + v0.w * v0.w +
              v1.x * v1.x + v1.y * v1.y + v1.z * v1.z + v1.w * v1.w;

    __shared__ float rs[16], rq[16], stat[2];
#pragma unroll
    for (int o = 16; o; o >>= 1) {
        s += __shfl_xor_sync(0xffffffffu, s, o);
        q += __shfl_xor_sync(0xffffffffu, q, o);
    }
    const int wid = t >> 5, lane = t & 31;
    if (!lane) { rs[wid] = s; rq[wid] = q; }
    __syncthreads();
    if (t < 32) {
        float a  = (t < 16) ? rs[t] : 0.f;
        float b2 = (t < 16) ? rq[t] : 0.f;
#pragma unroll
        for (int o = 8; o; o >>= 1) {
            a  += __shfl_xor_sync(0xffffffffu, a, o);
            b2 += __shfl_xor_sync(0xffffffffu, b2, o);
        }
        if (!t) {
            float mu = a * (1.0f / HID);
            float var = b2 * (1.0f / HID) - mu * mu;
            stat[0] = mu;
            stat[1] = rsqrtf(var + 1e-5f);
        }
    }
    __syncthreads();
    const float mu = stat[0], rstd = stat[1];

    const float4* x4 = (const float4*)(x + row * HID);
    const float4* g4 = (const float4*)lng;
    const float4* b4 = (const float4*)lnb;
    float4* o4 = (float4*)(out + row * HID);

    auto act = [&](float yv, float gg, float bb, float xv) {
        float u = (yv - mu) * rstd * gg + bb;
        return xv + 0.5f * u * (1.0f + erff(u * 0.70710678118f));
    };
#pragma unroll
    for (int half = 0; half < 2; half++) {
        int idx = t + half * 512;
        float4 v = half ? v1 : v0;
        float4 gg = g4[idx], bb = b4[idx], xx = x4[idx];
        float4 rr;
        rr.x = act(v.x, gg.x, bb.x, xx.x);
        rr.y = act(v.y, gg.y, bb.y, xx.y);
        rr.z = act(v.z, gg.z, bb.z, xx.z);
        rr.w = act(v.w, gg.w, bb.w, xx.w);
        o4[idx] = rr;
    }
}

// ---------------- launcher ----------------
extern "C" void kernel_launch(void* const* d_in, const int* in_sizes, int n_in,
                              void* d_out, int out_size) {
    const float* x      = (const float*)d_in[0];
    const float* Wih_f  = (const float*)d_in[1];
    const float* Whh_f  = (const float*)d_in[2];
    const float* bih_f  = (const float*)d_in[3];
    const float* bhh_f  = (const float*)d_in[4];
    const float* Wih_b  = (const float*)d_in[5];
    const float* Whh_b  = (const float*)d_in[6];
    const float* bih_b  = (const float*)d_in[7];
    const float* bhh_b  = (const float*)d_in[8];
    const float* projW  = (const float*)d_in[9];
    const float* projb  = (const float*)d_in[10];
    const float* lng    = (const float*)d_in[11];
    const float* lnb    = (const float*)d_in[12];
    float* out = (float*)d_out;

    static bool attr_done = false;
    if (!attr_done) {
        cudaFuncSetAttribute(k_tcgemm, cudaFuncAttributeMaxDynamicSharedMemorySize, SMEM_BYTES);
        attr_done = true;
    }

    k_cvt<<<8192, 256>>>((const float4*)x, Wih_f, Whh_f, bih_f, bhh_f,
                         Wih_b, Whh_b, bih_b, bhh_b, projW);
    k_tcgemm<<<dim3(TOT / TCN, BT / TCM), 256, SMEM_BYTES>>>(0, nullptr);
    k_lstm0<<<(BDIM * 512) / 256, 256>>>();
    for (int s = 1; s < TS; s++) k_lstm<<<dim3(8, 256, 2), 256>>>(s);
    k_tcgemm<<<dim3(HID / TCN, BDIM / TCM), 256, SMEM_BYTES>>>(1, projb);
    k_ln<<<16384, 512>>>(x, lng, lnb, out);
}

// round 15
// speedup vs baseline: 1.4175x; 1.0296x over previous
#include <cuda_runtime.h>
#include <cuda_fp16.h>
#include <cstdint>

#define BDIM  16384
#define HID   4096
#define TS    4
#define CH    1024
#define LHH   256
#define G4    1024
#define TOT   2048
#define BT    65536

#if defined(__CUDA_ARCH__) && (defined(__CUDA_ARCH_FEAT_SM103_ALL) || defined(__CUDA_ARCH_FEAT_SM100_ALL))
#define TC_OK 1
#endif

// ---------------- scratch (device globals: allocation-free) ----------------
__device__ __align__(256) __half g_Xh[(size_t)BT * CH];
__device__ __align__(256) __half g_G[(size_t)BT * TOT];
__device__ __align__(256) __half g_Wc[TOT * CH];
__device__ __align__(256) __half g_Whh[2][G4 * LHH];
__device__ __align__(16)  float  g_bias[2][G4];
__device__ __align__(256) __half g_projW[(size_t)HID * TOT];
__device__ __align__(256) __half g_flat[(size_t)BDIM * TOT];
__device__ __align__(256) float  g_c[2][(size_t)BDIM * LHH];
__device__ __align__(256) __half g_yh[(size_t)BDIM * HID];   // fp16 proj output

// ---------------- generic helpers ----------------
__device__ __forceinline__ void cp16(void* smem, const void* gmem) {
    uint32_t s = (uint32_t)__cvta_generic_to_shared(smem);
    asm volatile("cp.async.cg.shared.global [%0], [%1], 16;\n" ::"r"(s), "l"(gmem));
}
__device__ __forceinline__ void cp16s(uint32_t s, const void* gmem) {
    asm volatile("cp.async.cg.shared.global [%0], [%1], 16;\n" ::"r"(s), "l"(gmem));
}
__device__ __forceinline__ void cp_commit() { asm volatile("cp.async.commit_group;\n"); }
template <int N>
__device__ __forceinline__ void cp_wait() { asm volatile("cp.async.wait_group %0;\n" ::"n"(N)); }

__device__ __forceinline__ float tanha(float x) {
    float y; asm("tanh.approx.f32 %0, %1;" : "=f"(y) : "f"(x)); return y;
}
__device__ __forceinline__ float sigt(float x) { return 0.5f * tanha(0.5f * x) + 0.5f; }

#ifdef TC_OK
__device__ __forceinline__ uint32_t elect1() {
    uint32_t p;
    asm volatile("{\n\t.reg .pred p;\n\telect.sync _|p, 0xFFFFFFFF;\n\tselp.b32 %0,1,0,p;\n\t}"
                 : "=r"(p));
    return p;
}
__device__ __forceinline__ void mbar_init(uint32_t mbar, uint32_t cnt) {
    asm volatile("mbarrier.init.shared.b64 [%0], %1;" ::"r"(mbar), "r"(cnt) : "memory");
}
__device__ __forceinline__ void mbar_wait(uint32_t mbar, uint32_t parity) {
    asm volatile(
        "{\n\t.reg .pred P;\n\t"
        "WL%=:\n\t"
        "mbarrier.try_wait.parity.acquire.cta.shared::cta.b64 P, [%0], %1, 0x989680;\n\t"
        "@P bra WD%=;\n\t"
        "bra WL%=;\n\t"
        "WD%=:\n\t}" ::"r"(mbar), "r"(parity) : "memory");
}
__device__ __forceinline__ void tc_commit(uint32_t mbar) {
    asm volatile(
        "tcgen05.commit.cta_group::1.mbarrier::arrive::one.shared::cluster.b64 [%0];"
        ::"r"(mbar) : "memory");
}
__device__ __forceinline__ void mma_f16_ss(uint32_t d, uint64_t a, uint64_t b,
                                           uint32_t idesc, uint32_t en) {
    asm volatile(
        "{\n\t.reg .pred p;\n\tsetp.ne.u32 p, %4, 0;\n\t"
        "tcgen05.mma.cta_group::1.kind::f16 [%0], %1, %2, %3, {%5,%5,%5,%5}, p;\n\t}"
        ::"r"(d), "l"(a), "l"(b), "r"(idesc), "r"(en), "r"(0u) : "memory");
}
#define LDTM_X32(r, addr)                                                                  \
    asm volatile(                                                                          \
        "tcgen05.ld.sync.aligned.32x32b.x32.b32 "                                          \
        "{%0,%1,%2,%3,%4,%5,%6,%7,%8,%9,%10,%11,%12,%13,%14,%15,"                          \
        "%16,%17,%18,%19,%20,%21,%22,%23,%24,%25,%26,%27,%28,%29,%30,%31}, [%32];"        \
        : "=r"((r)[0]), "=r"((r)[1]), "=r"((r)[2]), "=r"((r)[3]), "=r"((r)[4]),            \
          "=r"((r)[5]), "=r"((r)[6]), "=r"((r)[7]), "=r"((r)[8]), "=r"((r)[9]),            \
          "=r"((r)[10]), "=r"((r)[11]), "=r"((r)[12]), "=r"((r)[13]), "=r"((r)[14]),       \
          "=r"((r)[15]), "=r"((r)[16]), "=r"((r)[17]), "=r"((r)[18]), "=r"((r)[19]),       \
          "=r"((r)[20]), "=r"((r)[21]), "=r"((r)[22]), "=r"((r)[23]), "=r"((r)[24]),       \
          "=r"((r)[25]), "=r"((r)[26]), "=r"((r)[27]), "=r"((r)[28]), "=r"((r)[29]),       \
          "=r"((r)[30]), "=r"((r)[31])                                                     \
        : "r"(addr))
__device__ __forceinline__ void tc_wait_ld() {
    asm volatile("tcgen05.wait::ld.sync.aligned;" ::: "memory");
}
#endif  // TC_OK

// ---------------- big GEMM kernel: C tiles of 128 x 256, K-major fp16 ----------------
#define TCM 128
#define TCN 256
#define SMEM_BYTES 101376

__global__ void __launch_bounds__(256, 1) k_tcgemm(int mode, const float* __restrict__ bias) {
    extern __shared__ char dsm[];
    uint32_t smraw = (uint32_t)__cvta_generic_to_shared(dsm);
    uint32_t smb = (smraw + 1023) & ~1023u;
    char* base = dsm + (smb - smraw);

    const int tid = threadIdx.x, lane = tid & 31, wid = tid >> 5;

    const __half* A;
    const __half* B;
    int K;
    if (mode == 0) { A = g_Xh;   B = g_Wc;    K = CH;  }
    else           { A = g_flat; B = g_projW; K = TOT; }

    const size_t row0 = (size_t)blockIdx.y * TCM;
    const int n0 = blockIdx.x * TCN;
    const __half* Ag = A + row0 * K;
    const __half* Bg = B + (size_t)n0 * K;

#ifdef TC_OK
    const uint32_t smA0 = smb + 1024;
    const uint32_t smA1 = smA0 + 16384;
    const uint32_t smB0 = smA1 + 16384;
    const uint32_t smB1 = smB0 + 32768;
    const uint32_t mbar0 = smb + 8, mbar1 = smb + 16;
    const int NT = K / 64;

    if (wid == 0) {
        asm volatile("tcgen05.alloc.cta_group::1.sync.aligned.shared::cta.b32 [%0], %1;"
                     ::"r"(smb), "r"(256u) : "memory");
        asm volatile("tcgen05.relinquish_alloc_permit.cta_group::1.sync.aligned;" ::: "memory");
    }
    if (tid == 0) { mbar_init(mbar0, 1); mbar_init(mbar1, 1); }
    __syncthreads();
    uint32_t tmem;
    asm volatile("ld.shared.b32 %0, [%1];" : "=r"(tmem) : "r"(smb));

    const uint32_t el = (wid == 0) ? elect1() : 0u;
    constexpr uint32_t IDESC = (1u << 4) | ((TCN / 8) << 17) | ((TCM / 16) << 24);
    const uint64_t DBASE = (2ull << 61) | (1ull << 46) | (64ull << 32) | (1ull << 16);

    auto prefetch = [&](int kc, uint32_t sa, uint32_t sb) {
        const __half* Ab = Ag + kc * 64;
#pragma unroll
        for (int it = 0; it < 4; it++) {
            int o = tid + it * 256;
            int r = o >> 3, seg = o & 7;
            uint32_t off = (uint32_t)(r * 128 + seg * 16);
            cp16s(sa + (off ^ ((off >> 3) & 0x70)), Ab + (size_t)r * K + seg * 8);
        }
        const __half* Bb = Bg + kc * 64;
#pragma unroll
        for (int it = 0; it < 8; it++) {
            int o = tid + it * 256;
            int r = o >> 3, seg = o & 7;
            uint32_t off = (uint32_t)(r * 128 + seg * 16);
            cp16s(sb + (off ^ ((off >> 3) & 0x70)), Bb + (size_t)r * K + seg * 8);
        }
        cp_commit();
    };

    prefetch(0, smA0, smB0);
    int ph0 = 0, ph1 = 0;

    for (int i = 0; i < NT; i++) {
        const int b = i & 1;
        if (i + 1 < NT) {
            const int bb = (i + 1) & 1;
            if (i >= 1) {
                if (bb) { mbar_wait(mbar1, (uint32_t)ph1); ph1 ^= 1; }
                else    { mbar_wait(mbar0, (uint32_t)ph0); ph0 ^= 1; }
            }
            prefetch(i + 1, bb ? smA1 : smA0, bb ? smB1 : smB0);
            cp_wait<1>();
        } else {
            cp_wait<0>();
        }
        __syncthreads();
        if (wid == 0 && el) {
            asm volatile("fence.proxy.async.shared::cta;" ::: "memory");
            uint64_t da = DBASE | (((uint64_t)((b ? smA1 : smA0) >> 4)) & 0x3FFF);
            uint64_t db = DBASE | (((uint64_t)((b ? smB1 : smB0) >> 4)) & 0x3FFF);
#pragma unroll
            for (int s = 0; s < 4; s++)
                mma_f16_ss(tmem, da + s * 2, db + s * 2, IDESC, (i > 0 || s > 0) ? 1u : 0u);
            tc_commit(b ? mbar1 : mbar0);
        }
    }
    {
        const int lb = (NT - 1) & 1;
        if (lb) mbar_wait(mbar1, (uint32_t)ph1);
        else    mbar_wait(mbar0, (uint32_t)ph0);
    }
    asm volatile("tcgen05.fence::after_thread_sync;" ::: "memory");
    __syncthreads();

    uint32_t r[32];
    const int myrow = wid * 32 + lane;
    if (mode == 0) {
        __half* sO = (__half*)(base + 1024);  // [128][258]
        if (wid < 4) {
#pragma unroll
            for (int g = 0; g < 8; g++) {
                LDTM_X32(r, tmem + g * 32);
                tc_wait_ld();
#pragma unroll
                for (int c = 0; c < 32; c += 2) {
                    __half2 h = __floats2half2_rn(__uint_as_float(r[c]), __uint_as_float(r[c + 1]));
                    *(__half2*)&sO[myrow * 258 + g * 32 + c] = h;
                }
            }
        }
        __syncthreads();
#pragma unroll 4
        for (int it = 0; it < 64; it++) {
            int idx = tid + it * 256;
            int cp = idx & 127, row = idx >> 7;
            __half2 v = *(__half2*)&sO[row * 258 + cp * 2];
            *(__half2*)&g_G[(row0 + row) * TOT + n0 + cp * 2] = v;
        }
    } else {
        float* sF = (float*)(base + 1024);    // [128][129]
#pragma unroll
        for (int p = 0; p < 2; p++) {
            if (wid < 4) {
#pragma unroll
                for (int g = 0; g < 4; g++) {
                    LDTM_X32(r, tmem + p * 128 + g * 32);
                    tc_wait_ld();
#pragma unroll
                    for (int c = 0; c < 32; c++)
                        sF[myrow * 129 + g * 32 + c] = __uint_as_float(r[c]);
                }
            }
            __syncthreads();
            // write half2: 128 rows x 64 half2 per pass
#pragma unroll 4
            for (int it = 0; it < 32; it++) {
                int idx = tid + it * 256;
                int c2 = idx & 63, row = idx >> 6;
                int gc = n0 + p * 128 + c2 * 2;
                __half2 h = __floats2half2_rn(sF[row * 129 + c2 * 2]     + bias[gc],
                                              sF[row * 129 + c2 * 2 + 1] + bias[gc + 1]);
                *(__half2*)&g_yh[(row0 + row) * HID + gc] = h;
            }
            __syncthreads();
        }
    }
    __syncthreads();
    if (wid == 0) {
        asm volatile("tcgen05.dealloc.cta_group::1.sync.aligned.b32 %0, %1;"
                     ::"r"(tmem), "r"(256u));
    }
#else
    // HMMA fallback (family cubin)
    (void)base;
    constexpr int SKH = 40;
    constexpr int STG = (TCM + TCN) * SKH * 2;
    const uint32_t sA_[3] = {smb, smb + STG, smb + 2 * STG};

    float acc[128];
#pragma unroll
    for (int i = 0; i < 128; i++) acc[i] = 0.f;

    const int wm = (wid & 1) * 64;
    const int wn = (wid >> 1) * 64;
    const int KT = K / 32;

    auto issue = [&](int kt, int s) {
        const uint32_t sa = sA_[s];
        const uint32_t sb = sA_[s] + TCM * SKH * 2;
        const __half* Ab = Ag + kt * 32;
#pragma unroll
        for (int i = 0; i < 2; i++) {
            int o = tid + i * 256;
            int rr = o >> 2, c = o & 3;
            cp16s(sa + rr * (SKH * 2) + c * 16, Ab + (size_t)rr * K + c * 8);
        }
        const __half* Bb = Bg + kt * 32;
#pragma unroll
        for (int i = 0; i < 4; i++) {
            int o = tid + i * 256;
            int rr = o >> 2, c = o & 3;
            cp16s(sb + rr * (SKH * 2) + c * 16, Bb + (size_t)rr * K + c * 8);
        }
        cp_commit();
    };

    issue(0, 0);
    if (KT > 1) issue(1, 1);
    if (KT > 2) issue(2, 2);

    for (int kt = 0; kt < KT; kt++) {
        const int rem = KT - 1 - kt;
        if (rem >= 2)      cp_wait<2>();
        else if (rem == 1) cp_wait<1>();
        else               cp_wait<0>();
        __syncthreads();

        const __half* cA = (const __half*)(dsm + (sA_[kt % 3] - smraw));
        const __half* cB = cA + TCM * SKH;
#pragma unroll
        for (int kk = 0; kk < 2; kk++) {
            const int kb = kk * 16 + (lane & 3) * 2;
            uint32_t afr[4][4], bfr[8][2];
#pragma unroll
            for (int mf = 0; mf < 4; mf++) {
                int rr = wm + mf * 16 + (lane >> 2);
                afr[mf][0] = *(const uint32_t*)(cA + rr * SKH + kb);
                afr[mf][1] = *(const uint32_t*)(cA + (rr + 8) * SKH + kb);
                afr[mf][2] = *(const uint32_t*)(cA + rr * SKH + kb + 8);
                afr[mf][3] = *(const uint32_t*)(cA + (rr + 8) * SKH + kb + 8);
            }
#pragma unroll
            for (int nf = 0; nf < 8; nf++) {
                int n = wn + nf * 8 + (lane >> 2);
                bfr[nf][0] = *(const uint32_t*)(cB + n * SKH + kb);
                bfr[nf][1] = *(const uint32_t*)(cB + n * SKH + kb + 8);
            }
#pragma unroll
            for (int mf = 0; mf < 4; mf++)
#pragma unroll
                for (int nf = 0; nf < 8; nf++) {
                    float* c = &acc[(mf * 8 + nf) * 4];
                    asm volatile(
                        "mma.sync.aligned.m16n8k16.row.col.f32.f16.f16.f32 "
                        "{%0,%1,%2,%3},{%4,%5,%6,%7},{%8,%9},{%0,%1,%2,%3};\n"
                        : "+f"(c[0]), "+f"(c[1]), "+f"(c[2]), "+f"(c[3])
                        : "r"(afr[mf][0]), "r"(afr[mf][1]), "r"(afr[mf][2]), "r"(afr[mf][3]),
                          "r"(bfr[nf][0]), "r"(bfr[nf][1]));
                }
        }
        __syncthreads();
        if (kt + 3 < KT) issue(kt + 3, (kt + 3) % 3);
    }

    if (mode == 0) {
#pragma unroll
        for (int mf = 0; mf < 4; mf++)
#pragma unroll
            for (int nf = 0; nf < 8; nf++) {
                const float* c = &acc[(mf * 8 + nf) * 4];
                int rr = wm + mf * 16 + (lane >> 2);
                int n = n0 + wn + nf * 8 + (lane & 3) * 2;
                __half2 h0 = __floats2half2_rn(c[0], c[1]);
                __half2 h1 = __floats2half2_rn(c[2], c[3]);
                *(__half2*)&g_G[(row0 + rr) * TOT + n]     = h0;
                *(__half2*)&g_G[(row0 + rr + 8) * TOT + n] = h1;
            }
    } else {
#pragma unroll
        for (int mf = 0; mf < 4; mf++)
#pragma unroll
            for (int nf = 0; nf < 8; nf++) {
                const float* c = &acc[(mf * 8 + nf) * 4];
                int rr = wm + mf * 16 + (lane >> 2);
                int n = n0 + wn + nf * 8 + (lane & 3) * 2;
                float b0 = bias[n], b1 = bias[n + 1];
                __half2 h0 = __floats2half2_rn(c[0] + b0, c[1] + b1);
                __half2 h1 = __floats2half2_rn(c[2] + b0, c[3] + b1);
                *(__half2*)&g_yh[(row0 + rr) * HID + n]     = h0;
                *(__half2*)&g_yh[(row0 + rr + 8) * HID + n] = h1;
            }
    }
#endif
}

// ---------------- 2-stage HMMA core for the recurrent GEMM (round-8 proven) ----------------
template <int BM, int BN, int WROWS, int WCOLS>
__device__ __forceinline__ void gemm_core(
    const __half* __restrict__ Aptr, int lda,
    const __half* __restrict__ Bptr, int ldb,
    int K, __half* sA, __half* sB, float* acc)
{
    constexpr int BK = 32, SK = 40;
    constexpr int THREADS = WROWS * WCOLS * 32;
    constexpr int WM = BM / WROWS, WN = BN / WCOLS;
    constexpr int MF = WM / 16, NF = WN / 8;

    const int tid  = threadIdx.x;
    const int lane = tid & 31, warp = tid >> 5;
    const int wm = (warp % WROWS) * WM;
    const int wn = (warp / WROWS) * WN;
    const int KT = K / BK;

    auto issue = [&](int kt, int buf) {
        const __half* Ag = Aptr + kt * BK;
#pragma unroll
        for (int i = 0; i < (BM * 4) / THREADS; i++) {
            int c = tid + i * THREADS;
            int r = c >> 2, kc = c & 3;
            cp16(sA + buf * (BM * SK) + r * SK + kc * 8, Ag + (size_t)r * lda + kc * 8);
        }
        const __half* Bg = Bptr + kt * BK;
#pragma unroll
        for (int i = 0; i < (BN * 4) / THREADS; i++) {
            int c = tid + i * THREADS;
            int r = c >> 2, kc = c & 3;
            cp16(sB + buf * (BN * SK) + r * SK + kc * 8, Bg + (size_t)r * ldb + kc * 8);
        }
        cp_commit();
    };

    issue(0, 0);
    for (int kt = 0; kt < KT; kt++) {
        if (kt + 1 < KT) { issue(kt + 1, (kt + 1) & 1); cp_wait<1>(); }
        else             { cp_wait<0>(); }
        __syncthreads();
        const __half* cA = sA + (kt & 1) * (BM * SK);
        const __half* cB = sB + (kt & 1) * (BN * SK);
#pragma unroll
        for (int kk = 0; kk < 2; kk++) {
            uint32_t afr[MF][4], bfr[NF][2];
            const int kb = kk * 16 + (lane & 3) * 2;
#pragma unroll
            for (int mf = 0; mf < MF; mf++) {
                int rr = wm + mf * 16 + (lane >> 2);
                afr[mf][0] = *(const uint32_t*)(cA + rr * SK + kb);
                afr[mf][1] = *(const uint32_t*)(cA + (rr + 8) * SK + kb);
                afr[mf][2] = *(const uint32_t*)(cA + rr * SK + kb + 8);
                afr[mf][3] = *(const uint32_t*)(cA + (rr + 8) * SK + kb + 8);
            }
#pragma unroll
            for (int nf = 0; nf < NF; nf++) {
                int n = wn + nf * 8 + (lane >> 2);
                bfr[nf][0] = *(const uint32_t*)(cB + n * SK + kb);
                bfr[nf][1] = *(const uint32_t*)(cB + n * SK + kb + 8);
            }
#pragma unroll
            for (int mf = 0; mf < MF; mf++)
#pragma unroll
                for (int nf = 0; nf < NF; nf++) {
                    float* c = &acc[((mf * NF) + nf) * 4];
                    asm volatile(
                        "mma.sync.aligned.m16n8k16.row.col.f32.f16.f16.f32 "
                        "{%0,%1,%2,%3},{%4,%5,%6,%7},{%8,%9},{%0,%1,%2,%3};\n"
                        : "+f"(c[0]), "+f"(c[1]), "+f"(c[2]), "+f"(c[3])
                        : "r"(afr[mf][0]), "r"(afr[mf][1]), "r"(afr[mf][2]), "r"(afr[mf][3]),
                          "r"(bfr[nf][0]), "r"(bfr[nf][1]));
                }
        }
        __syncthreads();
    }
}

// ---------------- conversion kernels (round-8) ----------------
__global__ void __launch_bounds__(256) k_cvt_x(const float4* __restrict__ x4) {
    uint2* o = (uint2*)g_Xh;
    const size_t n4 = (size_t)BT * CH / 4;
    for (size_t i = blockIdx.x * (size_t)blockDim.x + threadIdx.x; i < n4;
         i += (size_t)gridDim.x * blockDim.x) {
        float4 v = x4[i];
        __half2 a = __floats2half2_rn(v.x, v.y);
        __half2 b = __floats2half2_rn(v.z, v.w);
        o[i] = make_uint2(*(uint32_t*)&a, *(uint32_t*)&b);
    }
}

__global__ void __launch_bounds__(256) k_cvt_w(
    const float* __restrict__ Wih_f, const float* __restrict__ Whh_f,
    const float* __restrict__ bih_f, const float* __restrict__ bhh_f,
    const float* __restrict__ Wih_b, const float* __restrict__ Whh_b,
    const float* __restrict__ bih_b, const float* __restrict__ bhh_b,
    const float* __restrict__ projW)
{
    const int S0 = TOT * CH;
    const int S1 = 2 * G4 * LHH;
    const int S2 = 2 * G4;
    const int S3 = HID * TOT;
    const int total = S0 + S1 + S2 + S3;
    for (int idx = blockIdx.x * blockDim.x + threadIdx.x; idx < total;
         idx += gridDim.x * blockDim.x) {
        if (idx < S0) {
            int p = idx >> 10, k = idx & 1023;
            int dir = p >> 10, q = p & 1023;
            int j = q >> 2, gi = q & 3;
            const float* W = dir ? Wih_b : Wih_f;
            g_Wc[idx] = __float2half_rn(W[(gi * LHH + j) * CH + k]);
        } else if (idx < S0 + S1) {
            int i = idx - S0;
            int dir = (i >= G4 * LHH);
            int ii = i - dir * (G4 * LHH);
            int p = ii >> 8, k = ii & 255;
            int j = p >> 2, gi = p & 3;
            const float* W = dir ? Whh_b : Whh_f;
            g_Whh[dir][p * LHH + k] = __float2half_rn(W[(gi * LHH + j) * LHH + k]);
        } else if (idx < S0 + S1 + S2) {
            int i = idx - S0 - S1;
            int dir = (i >= G4);
            int p = i - dir * G4;
            int j = p >> 2, gi = p & 3;
            const float* b1 = dir ? bih_b : bih_f;
            const float* b2 = dir ? bhh_b : bhh_f;
            g_bias[dir][p] = b1[gi * LHH + j] + b2[gi * LHH + j];
        } else {
            int i = idx - S0 - S1 - S2;
            g_projW[i] = __float2half_rn(projW[i]);
        }
    }
}

// ---------------- LSTM step 0: pure elementwise (c0 = 0) ----------------
__global__ void __launch_bounds__(256) k_lstm0() {
    int idx = blockIdx.x * 256 + threadIdx.x;
    int j = idx & 255;
    int dir = (idx >> 8) & 1;
    size_t row = (size_t)(idx >> 9);
    int t = dir ? (TS - 1) : 0;

    const __half* Gp = g_G + ((row * TS + t) * TOT + dir * G4 + j * 4);
    uint2 gw = *(const uint2*)Gp;
    __half2 g01 = *(__half2*)&gw.x;
    __half2 g23 = *(__half2*)&gw.y;
    float4 bb = *(const float4*)&g_bias[dir][j * 4];

    float gi = __low2float(g01)  + bb.x;
    float gg = __low2float(g23)  + bb.z;
    float go = __high2float(g23) + bb.w;

    float c_new = sigt(gi) * tanha(gg);
    float h = sigt(go) * tanha(c_new);
    g_c[dir][row * LHH + j] = c_new;
    g_flat[row * TOT + t * 512 + dir * 256 + j] = __float2half_rn(h);
}

// ---------------- LSTM steps 1..3: recurrent GEMM + cell (round-8 proven) ----------------
__global__ void __launch_bounds__(256) k_lstm(int step) {
    __shared__ __align__(16) char smraw[64 * 132 * 4];
    __half* sA = (__half*)smraw;
    __half* sB = (__half*)(smraw + 10240);
    float*  sG = (float*)smraw;

    const int dir  = blockIdx.z;
    const int tcur = dir ? (TS - 1 - step) : step;
    const int tprev = dir ? (tcur + 1) : (tcur - 1);

    float acc[32];
#pragma unroll
    for (int i = 0; i < 32; i++) acc[i] = 0.f;

    {
        const __half* A  = g_flat + (size_t)blockIdx.y * 64 * TOT + tprev * 512 + dir * 256;
        const __half* Bm = g_Whh[dir] + (size_t)blockIdx.x * 128 * LHH;
        gemm_core<64, 128, 2, 4>(A, TOT, Bm, LHH, LHH, sA, sB, acc);
    }
    __syncthreads();

    const int lane = threadIdx.x & 31, warp = threadIdx.x >> 5;
    const int wm = (warp % 2) * 32, wn = (warp / 2) * 32;
#pragma unroll
    for (int mf = 0; mf < 2; mf++)
#pragma unroll
        for (int nf = 0; nf < 4; nf++) {
            const float* c = &acc[(mf * 4 + nf) * 4];
            int rr = wm + mf * 16 + (lane >> 2);
            int n = wn + nf * 8 + (lane & 3) * 2;
            sG[rr * 132 + n]           = c[0];
            sG[rr * 132 + n + 1]       = c[1];
            sG[(rr + 8) * 132 + n]     = c[2];
            sG[(rr + 8) * 132 + n + 1] = c[3];
        }
    __syncthreads();

    const size_t row0 = (size_t)blockIdx.y * 64;
    const int n0 = blockIdx.x * 128;
#pragma unroll
    for (int it = 0; it < 8; it++) {
        int item = threadIdx.x + it * 256;
        int m = item >> 5, jl = item & 31;
        size_t rb = row0 + m;
        int j = (n0 >> 2) + jl;

        float4 gsum = *(float4*)&sG[m * 132 + jl * 4];
        const __half* Gp = g_G + ((rb * TS + tcur) * TOT + dir * G4 + n0 + jl * 4);
        uint2 gw = *(const uint2*)Gp;
        __half2 g01 = *(__half2*)&gw.x;
        __half2 g23 = *(__half2*)&gw.y;
        float4 bb = *(const float4*)&g_bias[dir][n0 + jl * 4];

        float gi = gsum.x + __low2float(g01)  + bb.x;
        float gf = gsum.y + __high2float(g01) + bb.y;
        float gg = gsum.z + __low2float(g23)  + bb.z;
        float go = gsum.w + __high2float(g23) + bb.w;

        float c_old = g_c[dir][rb * LHH + j];
        float c_new = sigt(gf) * c_old + sigt(gi) * tanha(gg);
        float h = sigt(go) * tanha(c_new);
        g_c[dir][rb * LHH + j] = c_new;
        g_flat[rb * TOT + tcur * 512 + dir * 256 + j] = __float2half_rn(h);
    }
}

// ---------------- LayerNorm + exact GELU + residual (reads fp16 y) ----------------
__global__ void __launch_bounds__(512) k_ln(
    const float* __restrict__ x, const float* __restrict__ lng,
    const float* __restrict__ lnb, float* __restrict__ out)
{
    const size_t row = blockIdx.x;
    const int t = threadIdx.x;
    const uint4* y8 = (const uint4*)(g_yh + row * HID);   // 8 halves / thread
    uint4 yv = y8[t];
    __half2 h0 = *(__half2*)&yv.x, h1 = *(__half2*)&yv.y;
    __half2 h2 = *(__half2*)&yv.z, h3 = *(__half2*)&yv.w;
    float v[8];
    v[0] = __low2float(h0); v[1] = __high2float(h0);
    v[2] = __low2float(h1); v[3] = __high2float(h1);
    v[4] = __low2float(h2); v[5] = __high2float(h2);
    v[6] = __low2float(h3); v[7] = __high2float(h3);

    float s = 0.f, q = 0.f;
#pragma unroll
    for (int i = 0; i < 8; i++) { s += v[i]; q += v[i] * v[i]; }

    __shared__ float rs[16], rq[16], stat[2];
#pragma unroll
    for (int o = 16; o; o >>= 1) {
        s += __shfl_xor_sync(0xffffffffu, s, o);
        q += __shfl_xor_sync(0xffffffffu, q, o);
    }
    const int wid = t >> 5, lane = t & 31;
    if (!lane) { rs[wid] = s; rq[wid] = q; }
    __syncthreads();
    if (t < 32) {
        float a  = (t < 16) ? rs[t] : 0.f;
        float b2 = (t < 16) ? rq[t] : 0.f;
#pragma unroll
        for (int o = 8; o; o >>= 1) {
            a  += __shfl_xor_sync(0xffffffffu, a, o);
            b2 += __shfl_xor_sync(0xffffffffu, b2, o);
        }
        if (!t) {
            float mu = a * (1.0f / HID);
            float var = b2 * (1.0f / HID) - mu * mu;
            stat[0] = mu;
            stat[1] = rsqrtf(var + 1e-5f);
        }
    }
    __syncthreads();
    const float mu = stat[0], rstd = stat[1];

    const float4* x4 = (const float4*)(x + row * HID);
    const float4* g4 = (const float4*)lng;
    const float4* b4 = (const float4*)lnb;
    float4* o4 = (float4*)(out + row * HID);

    auto act = [&](float yv_, float gg, float bb, float xv) {
        float u = (yv_ - mu) * rstd * gg + bb;
        return xv + 0.5f * u * (1.0f + erff(u * 0.70710678118f));
    };
#pragma unroll
    for (int half = 0; half < 2; half++) {
        int idx = t * 2 + half;          // float4 index; cols idx*4..idx*4+3 = t*8+half*4..
        float4 gg = g4[idx], bb = b4[idx], xx = x4[idx];
        float4 rr;
        rr.x = act(v[half * 4 + 0], gg.x, bb.x, xx.x);
        rr.y = act(v[half * 4 + 1], gg.y, bb.y, xx.y);
        rr.z = act(v[half * 4 + 2], gg.z, bb.z, xx.z);
        rr.w = act(v[half * 4 + 3], gg.w, bb.w, xx.w);
        o4[idx] = rr;
    }
}

// ---------------- launcher ----------------
extern "C" void kernel_launch(void* const* d_in, const int* in_sizes, int n_in,
                              void* d_out, int out_size) {
    const float* x      = (const float*)d_in[0];
    const float* Wih_f  = (const float*)d_in[1];
    const float* Whh_f  = (const float*)d_in[2];
    const float* bih_f  = (const float*)d_in[3];
    const float* bhh_f  = (const float*)d_in[4];
    const float* Wih_b  = (const float*)d_in[5];
    const float* Whh_b  = (const float*)d_in[6];
    const float* bih_b  = (const float*)d_in[7];
    const float* bhh_b  = (const float*)d_in[8];
    const float* projW  = (const float*)d_in[9];
    const float* projb  = (const float*)d_in[10];
    const float* lng    = (const float*)d_in[11];
    const float* lnb    = (const float*)d_in[12];
    float* out = (float*)d_out;

    static bool attr_done = false;
    if (!attr_done) {
        cudaFuncSetAttribute(k_tcgemm, cudaFuncAttributeMaxDynamicSharedMemorySize, SMEM_BYTES);
        attr_done = true;
    }

    k_cvt_x<<<4096, 256>>>((const float4*)x);
    k_cvt_w<<<2048, 256>>>(Wih_f, Whh_f, bih_f, bhh_f, Wih_b, Whh_b, bih_b, bhh_b, projW);
    k_tcgemm<<<dim3(TOT / TCN, BT / TCM), 256, SMEM_BYTES>>>(0, nullptr);
    k_lstm0<<<(BDIM * 512) / 256, 256>>>();
    for (int s = 1; s < TS; s++) k_lstm<<<dim3(8, 256, 2), 256>>>(s);
    k_tcgemm<<<dim3(HID / TCN, BDIM / TCM), 256, SMEM_BYTES>>>(1, projb);
    k_ln<<<16384, 512>>>(x, lng, lnb, out);
}